// round 2
// baseline (speedup 1.0000x reference)
#include <cuda_runtime.h>
#include <math.h>

#define DD   256
#define DD3  768
#define REL_TILE 8

// ---------------- device scratch (no allocations allowed) ----------------
__device__ float g_sub[DD];                 // seed subject embedding
__device__ float g_gi[DD3];                 // gi = r0 @ W_ih.T + b_ih  (constant across edges)
__device__ float g_WhhT[DD * DD3];          // W_hh transposed: [k][j]  (k in 0..255, j in 0..767)
__device__ float g_objWT[DD * DD];          // obj_W transposed: [k][j]
__device__ float g_objTable[2048 * DD];     // obj embedding per relation id
__device__ int   g_map[1 << 19];            // node -> edge inverse map (N <= 524288)

__device__ __forceinline__ float sigm(float x) { return 1.0f / (1.0f + expf(-x)); }

// ---------------- transposes (coalesced weight access downstream) ----------------
__global__ void transpose_whh_kernel(const float* __restrict__ W_hh) {
    __shared__ float tile[32][33];
    int x = blockIdx.x * 32 + threadIdx.x;   // col k  (0..255)
    int y = blockIdx.y * 32 + threadIdx.y;   // row j  (0..767)
    if (x < DD && y < DD3) tile[threadIdx.y][threadIdx.x] = W_hh[y * DD + x];
    __syncthreads();
    int oj = blockIdx.y * 32 + threadIdx.x;  // out col = j
    int ok = blockIdx.x * 32 + threadIdx.y;  // out row = k
    if (oj < DD3 && ok < DD) g_WhhT[ok * DD3 + oj] = tile[threadIdx.x][threadIdx.y];
}

__global__ void transpose_objw_kernel(const float* __restrict__ obj_W) {
    __shared__ float tile[32][33];
    int x = blockIdx.x * 32 + threadIdx.x;
    int y = blockIdx.y * 32 + threadIdx.y;
    if (x < DD && y < DD) tile[threadIdx.y][threadIdx.x] = obj_W[y * DD + x];
    __syncthreads();
    int oj = blockIdx.y * 32 + threadIdx.x;
    int ok = blockIdx.x * 32 + threadIdx.y;
    if (oj < DD && ok < DD) g_objWT[ok * DD + oj] = tile[threadIdx.x][threadIdx.y];
}

// ---------------- tiny serial chain: sub -> r0 -> gi  (one block, 768 threads) ----------------
__global__ void __launch_bounds__(DD3) tiny_chain_kernel(
    const float* __restrict__ enc, const float* __restrict__ mask,
    const float* __restrict__ W_ih, const float* __restrict__ W_hh,
    const float* __restrict__ b_ih, const float* __restrict__ b_hh,
    const float* __restrict__ sub_W, const float* __restrict__ sub_b)
{
    __shared__ float sm_mask[DD], sm_enc[DD], sm_sub[DD], sm_r0[DD];
    __shared__ float sm_gi0[DD3], sm_gh0[DD3];
    int t = threadIdx.x;

    if (t < DD) { sm_mask[t] = mask[t]; sm_enc[t] = enc[t]; }
    __syncthreads();

    // sub = tanh(mask @ sub_W.T + sub_b)
    if (t < DD) {
        float a = sub_b[t];
        const float4* w = (const float4*)(sub_W + t * DD);
        const float4* m = (const float4*)sm_mask;
        #pragma unroll 8
        for (int k = 0; k < DD / 4; k++) {
            float4 wv = w[k]; float4 mv = m[k];
            a += mv.x * wv.x + mv.y * wv.y + mv.z * wv.z + mv.w * wv.w;
        }
        float s = tanhf(a);
        sm_sub[t] = s;
        g_sub[t] = s;
    }
    __syncthreads();

    // gi0 = enc @ W_ih.T + b_ih ; gh0 = sub @ W_hh.T + b_hh
    {
        float a = b_ih[t], b = b_hh[t];
        const float4* wi = (const float4*)(W_ih + t * DD);
        const float4* wh = (const float4*)(W_hh + t * DD);
        const float4* ev = (const float4*)sm_enc;
        const float4* sv = (const float4*)sm_sub;
        #pragma unroll 8
        for (int k = 0; k < DD / 4; k++) {
            float4 w1 = wi[k], e4 = ev[k];
            a += e4.x * w1.x + e4.y * w1.y + e4.z * w1.z + e4.w * w1.w;
            float4 w2 = wh[k], s4 = sv[k];
            b += s4.x * w2.x + s4.y * w2.y + s4.z * w2.z + s4.w * w2.w;
        }
        sm_gi0[t] = a; sm_gh0[t] = b;
    }
    __syncthreads();

    // r0 = GRU combine
    if (t < DD) {
        float r = sigm(sm_gi0[t] + sm_gh0[t]);
        float z = sigm(sm_gi0[DD + t] + sm_gh0[DD + t]);
        float n = tanhf(sm_gi0[2 * DD + t] + r * sm_gh0[2 * DD + t]);
        sm_r0[t] = (1.0f - z) * n + z * sm_sub[t];
    }
    __syncthreads();

    // gi = r0 @ W_ih.T + b_ih
    {
        float a = b_ih[t];
        const float4* wi = (const float4*)(W_ih + t * DD);
        const float4* rv = (const float4*)sm_r0;
        #pragma unroll 8
        for (int k = 0; k < DD / 4; k++) {
            float4 wv = wi[k]; float4 r4 = rv[k];
            a += r4.x * wv.x + r4.y * wv.y + r4.z * wv.z + r4.w * wv.w;
        }
        g_gi[t] = a;
    }
}

// ---------------- per-relation obj table: obj_table[r] = tanh(GRU(gi, rel_emb[r]) @ obj_W.T + obj_b)
__global__ void __launch_bounds__(DD) rel_table_kernel(
    const float* __restrict__ rel_table,
    const float* __restrict__ b_hh,
    const float* __restrict__ obj_b,
    int R)
{
    __shared__ float h_s[REL_TILE][DD];
    __shared__ float rj_s[REL_TILE][DD];
    int tid = threadIdx.x;
    int rel0 = blockIdx.x * REL_TILE;

    #pragma unroll
    for (int r = 0; r < REL_TILE; r++) {
        int rel = rel0 + r;
        h_s[r][tid] = (rel < R) ? rel_table[rel * DD + tid] : 0.0f;
    }
    __syncthreads();

    float acc0[REL_TILE], acc1[REL_TILE], acc2[REL_TILE];
    float bh0 = b_hh[tid], bh1 = b_hh[DD + tid], bh2 = b_hh[2 * DD + tid];
    #pragma unroll
    for (int r = 0; r < REL_TILE; r++) { acc0[r] = bh0; acc1[r] = bh1; acc2[r] = bh2; }

    // gh = rel_emb @ W_hh.T  via transposed W (coalesced)
    for (int k = 0; k < DD; k++) {
        float w0 = g_WhhT[k * DD3 + tid];
        float w1 = g_WhhT[k * DD3 + DD + tid];
        float w2 = g_WhhT[k * DD3 + 2 * DD + tid];
        #pragma unroll
        for (int r = 0; r < REL_TILE; r++) {
            float hv = h_s[r][k];
            acc0[r] = fmaf(hv, w0, acc0[r]);
            acc1[r] = fmaf(hv, w1, acc1[r]);
            acc2[r] = fmaf(hv, w2, acc2[r]);
        }
    }

    float gi_r = g_gi[tid], gi_z = g_gi[DD + tid], gi_n = g_gi[2 * DD + tid];
    #pragma unroll
    for (int r = 0; r < REL_TILE; r++) {
        float rr = sigm(gi_r + acc0[r]);
        float zz = sigm(gi_z + acc1[r]);
        float nn = tanhf(gi_n + rr * acc2[r]);
        rj_s[r][tid] = (1.0f - zz) * nn + zz * h_s[r][tid];
    }
    __syncthreads();

    // obj = tanh(rj @ obj_W.T + obj_b)
    float ob = obj_b[tid];
    float acco[REL_TILE];
    #pragma unroll
    for (int r = 0; r < REL_TILE; r++) acco[r] = ob;
    for (int k = 0; k < DD; k++) {
        float w = g_objWT[k * DD + tid];
        #pragma unroll
        for (int r = 0; r < REL_TILE; r++)
            acco[r] = fmaf(rj_s[r][k], w, acco[r]);
    }
    #pragma unroll
    for (int r = 0; r < REL_TILE; r++) {
        int rel = rel0 + r;
        if (rel < R) g_objTable[rel * DD + tid] = tanhf(acco[r]);
    }
}

// ---------------- node -> edge inverse map ----------------
__global__ void map_init_kernel(int N) {
    int i = blockIdx.x * blockDim.x + threadIdx.x;
    if (i < N) g_map[i] = -1;
}
__global__ void map_scatter_kernel(const int* __restrict__ tail_ids, int E) {
    int e = blockIdx.x * blockDim.x + threadIdx.x;
    if (e < E) g_map[tail_ids[e]] = e;
}

// ---------------- final assembly: one 64-thread group per output row ----------------
__global__ void __launch_bounds__(256) assemble_kernel(
    float* __restrict__ out,
    const float* __restrict__ entity_table,
    const int* __restrict__ rel_ids,
    const int* __restrict__ tails_state,
    const int* __restrict__ origin_ids,
    const int* __restrict__ seed_p,
    int N)
{
    long long gid = (long long)blockIdx.x * blockDim.x + threadIdx.x;
    int lane = (int)(gid & 63);
    long long n = gid >> 6;
    if (n >= N) return;

    int e = g_map[n];
    float4 v;
    if (e >= 0) {
        if (tails_state[e] == 1) {
            const float4* src = (const float4*)(entity_table + (size_t)origin_ids[e] * DD);
            v = __ldcs(src + lane);                     // streaming: random 1KB gathers, no reuse
        } else {
            const float4* src = (const float4*)(g_objTable + (size_t)rel_ids[e] * DD);
            v = src[lane];                              // 1MB table: L2-resident
        }
    } else if ((int)n == *seed_p) {
        v = ((const float4*)g_sub)[lane];
    } else {
        v = make_float4(0.f, 0.f, 0.f, 0.f);
    }
    __stcs((float4*)out + n * (DD / 4) + lane, v);      // streaming store: don't thrash L2
}

// ---------------- launch ----------------
extern "C" void kernel_launch(void* const* d_in, const int* in_sizes, int n_in,
                              void* d_out, int out_size)
{
    const float* enc          = (const float*)d_in[0];
    const float* mask         = (const float*)d_in[1];
    const float* entity_table = (const float*)d_in[2];
    const float* rel_table    = (const float*)d_in[3];
    const float* W_ih         = (const float*)d_in[4];
    const float* W_hh         = (const float*)d_in[5];
    const float* b_ih         = (const float*)d_in[6];
    const float* b_hh         = (const float*)d_in[7];
    const float* sub_W        = (const float*)d_in[8];
    const float* sub_b        = (const float*)d_in[9];
    const float* obj_W        = (const float*)d_in[10];
    const float* obj_b        = (const float*)d_in[11];
    const int*   rel_ids      = (const int*)d_in[12];
    const int*   tail_ids     = (const int*)d_in[13];
    const int*   tails_state  = (const int*)d_in[14];
    const int*   origin_ids   = (const int*)d_in[15];
    const int*   seed_p       = (const int*)d_in[16];
    float*       out          = (float*)d_out;

    int E = in_sizes[12];
    int R = in_sizes[3] / DD;
    int N = out_size / DD;

    // 1) weight transposes (independent, cheap)
    transpose_whh_kernel<<<dim3(DD / 32, DD3 / 32), dim3(32, 32)>>>(W_hh);
    transpose_objw_kernel<<<dim3(DD / 32, DD / 32), dim3(32, 32)>>>(obj_W);

    // 2) sub -> r0 -> gi chain (single block)
    tiny_chain_kernel<<<1, DD3>>>(enc, mask, W_ih, W_hh, b_ih, b_hh, sub_W, sub_b);

    // 3) per-relation obj table
    rel_table_kernel<<<(R + REL_TILE - 1) / REL_TILE, DD>>>(rel_table, b_hh, obj_b, R);

    // 4) node->edge inverse map
    map_init_kernel<<<(N + 255) / 256, 256>>>(N);
    map_scatter_kernel<<<(E + 255) / 256, 256>>>(tail_ids, E);

    // 5) final gather/select/write of all N rows
    long long threads = (long long)N * 64;
    int blocks = (int)((threads + 255) / 256);
    assemble_kernel<<<blocks, 256>>>(out, entity_table, rel_ids, tails_state,
                                     origin_ids, seed_p, N);
}

// round 3
// speedup vs baseline: 1.1584x; 1.1584x over previous
#include <cuda_runtime.h>
#include <math.h>

#define DD   256
#define DD3  768

// ---------------- device scratch (no allocations allowed) ----------------
__device__ float g_sub[DD];                 // seed subject embedding
__device__ float g_gi[DD3];                 // gi = r0 @ W_ih.T + b_ih  (constant across edges)
__device__ float g_WhhT[DD * DD3];          // W_hh transposed: [k][j]
__device__ float g_objWT[DD * DD];          // obj_W transposed: [k][j]
__device__ float g_gh[1024 * DD3];          // rel_emb @ W_hh.T + b_hh   [R,768]
__device__ float g_rj[1024 * DD];           // GRU output per relation    [R,256]
__device__ float g_objTable[1024 * DD];     // obj embedding per relation [R,256]
__device__ int   g_map[1 << 19];            // node -> edge inverse map (N <= 524288)

__device__ __forceinline__ float sigm(float x) { return 1.0f / (1.0f + expf(-x)); }

// ---------------- merged transposes (coalesced weight access downstream) ----------------
__global__ void transpose_kernel(const float* __restrict__ W_hh,
                                 const float* __restrict__ obj_W) {
    __shared__ float tile[32][33];
    int bx = blockIdx.x, by = blockIdx.y;
    if (by < 24) {
        // W_hh [768][256] -> g_WhhT [256][768]
        int x = bx * 32 + threadIdx.x;   // k
        int y = by * 32 + threadIdx.y;   // j
        tile[threadIdx.y][threadIdx.x] = W_hh[y * DD + x];
        __syncthreads();
        int oj = by * 32 + threadIdx.x;
        int ok = bx * 32 + threadIdx.y;
        g_WhhT[ok * DD3 + oj] = tile[threadIdx.x][threadIdx.y];
    } else {
        // obj_W [256][256] -> g_objWT [256][256]
        int byy = by - 24;
        int x = bx * 32 + threadIdx.x;
        int y = byy * 32 + threadIdx.y;
        tile[threadIdx.y][threadIdx.x] = obj_W[y * DD + x];
        __syncthreads();
        int oj = byy * 32 + threadIdx.x;
        int ok = bx * 32 + threadIdx.y;
        g_objWT[ok * DD + oj] = tile[threadIdx.x][threadIdx.y];
    }
}

// ---------------- prep: block 0 = serial chain (sub -> r0 -> gi); others init map ----------------
__global__ void __launch_bounds__(DD3) prep_kernel(
    const float* __restrict__ enc, const float* __restrict__ mask,
    const float* __restrict__ W_ih, const float* __restrict__ W_hh,
    const float* __restrict__ b_ih, const float* __restrict__ b_hh,
    const float* __restrict__ sub_W, const float* __restrict__ sub_b,
    int N)
{
    if (blockIdx.x > 0) {
        int i = (blockIdx.x - 1) * DD3 + threadIdx.x;
        if (i < N) g_map[i] = -1;
        return;
    }

    __shared__ float sm_mask[DD], sm_enc[DD], sm_sub[DD], sm_r0[DD];
    __shared__ float sm_gi0[DD3], sm_gh0[DD3];
    int t = threadIdx.x;

    if (t < DD) { sm_mask[t] = mask[t]; sm_enc[t] = enc[t]; }
    __syncthreads();

    // sub = tanh(mask @ sub_W.T + sub_b)
    if (t < DD) {
        float a = sub_b[t];
        const float4* w = (const float4*)(sub_W + t * DD);
        const float4* m = (const float4*)sm_mask;
        #pragma unroll 8
        for (int k = 0; k < DD / 4; k++) {
            float4 wv = w[k]; float4 mv = m[k];
            a += mv.x * wv.x + mv.y * wv.y + mv.z * wv.z + mv.w * wv.w;
        }
        float s = tanhf(a);
        sm_sub[t] = s;
        g_sub[t] = s;
    }
    __syncthreads();

    // gi0 = enc @ W_ih.T + b_ih ; gh0 = sub @ W_hh.T + b_hh
    {
        float a = b_ih[t], b = b_hh[t];
        const float4* wi = (const float4*)(W_ih + t * DD);
        const float4* wh = (const float4*)(W_hh + t * DD);
        const float4* ev = (const float4*)sm_enc;
        const float4* sv = (const float4*)sm_sub;
        #pragma unroll 8
        for (int k = 0; k < DD / 4; k++) {
            float4 w1 = wi[k], e4 = ev[k];
            a += e4.x * w1.x + e4.y * w1.y + e4.z * w1.z + e4.w * w1.w;
            float4 w2 = wh[k], s4 = sv[k];
            b += s4.x * w2.x + s4.y * w2.y + s4.z * w2.z + s4.w * w2.w;
        }
        sm_gi0[t] = a; sm_gh0[t] = b;
    }
    __syncthreads();

    // r0 = GRU combine
    if (t < DD) {
        float r = sigm(sm_gi0[t] + sm_gh0[t]);
        float z = sigm(sm_gi0[DD + t] + sm_gh0[DD + t]);
        float n = tanhf(sm_gi0[2 * DD + t] + r * sm_gh0[2 * DD + t]);
        sm_r0[t] = (1.0f - z) * n + z * sm_sub[t];
    }
    __syncthreads();

    // gi = r0 @ W_ih.T + b_ih
    {
        float a = b_ih[t];
        const float4* wi = (const float4*)(W_ih + t * DD);
        const float4* rv = (const float4*)sm_r0;
        #pragma unroll 8
        for (int k = 0; k < DD / 4; k++) {
            float4 wv = wi[k]; float4 r4 = rv[k];
            a += r4.x * wv.x + r4.y * wv.y + r4.z * wv.z + r4.w * wv.w;
        }
        g_gi[t] = a;
    }
}

__global__ void map_scatter_kernel(const int* __restrict__ tail_ids, int E) {
    int e = blockIdx.x * blockDim.x + threadIdx.x;
    if (e < E) g_map[tail_ids[e]] = e;
}

// ---------------- tiled GEMM: C[M,NCOLS] = A[M,256] @ B[256,NCOLS] + bias (+tanh) ----------------
template<int NCOLS, bool DOTANH>
__global__ void __launch_bounds__(256) gemm_kernel(
    const float* __restrict__ A, const float* __restrict__ B,
    const float* __restrict__ bias, float* __restrict__ C, int M)
{
    __shared__ float As[64][36];   // 36: conflict-free rows, 144B stride (16B aligned)
    __shared__ float Bs[32][68];   // 68: 272B stride (16B aligned)
    int tid = threadIdx.x;
    int tx = tid & 15, ty = tid >> 4;
    int rbase = blockIdx.y * 64;
    int cbase = blockIdx.x * 64;
    float acc[4][4] = {};

    for (int k0 = 0; k0 < DD; k0 += 32) {
        #pragma unroll
        for (int i = 0; i < 2; i++) {
            int idx = tid + i * 256;
            // A tile: 64 rows x 32 k  (8 float4 per row)
            int ar = idx >> 3;
            int ac = (idx & 7) << 2;
            int gr = rbase + ar;
            float4 av = (gr < M) ? *(const float4*)(A + (size_t)gr * DD + k0 + ac)
                                 : make_float4(0.f, 0.f, 0.f, 0.f);
            *(float4*)&As[ar][ac] = av;
            // B tile: 32 k x 64 cols  (16 float4 per row)
            int bk = idx >> 4;
            int bc = (idx & 15) << 2;
            float4 bv = *(const float4*)(B + (size_t)(k0 + bk) * NCOLS + cbase + bc);
            *(float4*)&Bs[bk][bc] = bv;
        }
        __syncthreads();
        #pragma unroll
        for (int kk = 0; kk < 32; kk++) {
            float a0 = As[ty * 4 + 0][kk];
            float a1 = As[ty * 4 + 1][kk];
            float a2 = As[ty * 4 + 2][kk];
            float a3 = As[ty * 4 + 3][kk];
            float4 b = *(const float4*)&Bs[kk][tx * 4];
            acc[0][0] = fmaf(a0, b.x, acc[0][0]); acc[0][1] = fmaf(a0, b.y, acc[0][1]);
            acc[0][2] = fmaf(a0, b.z, acc[0][2]); acc[0][3] = fmaf(a0, b.w, acc[0][3]);
            acc[1][0] = fmaf(a1, b.x, acc[1][0]); acc[1][1] = fmaf(a1, b.y, acc[1][1]);
            acc[1][2] = fmaf(a1, b.z, acc[1][2]); acc[1][3] = fmaf(a1, b.w, acc[1][3]);
            acc[2][0] = fmaf(a2, b.x, acc[2][0]); acc[2][1] = fmaf(a2, b.y, acc[2][1]);
            acc[2][2] = fmaf(a2, b.z, acc[2][2]); acc[2][3] = fmaf(a2, b.w, acc[2][3]);
            acc[3][0] = fmaf(a3, b.x, acc[3][0]); acc[3][1] = fmaf(a3, b.y, acc[3][1]);
            acc[3][2] = fmaf(a3, b.z, acc[3][2]); acc[3][3] = fmaf(a3, b.w, acc[3][3]);
        }
        __syncthreads();
    }

    int col = cbase + tx * 4;
    float4 bv = *(const float4*)(bias + col);
    #pragma unroll
    for (int i = 0; i < 4; i++) {
        int gr = rbase + ty * 4 + i;
        if (gr < M) {
            float4 v;
            v.x = acc[i][0] + bv.x; v.y = acc[i][1] + bv.y;
            v.z = acc[i][2] + bv.z; v.w = acc[i][3] + bv.w;
            if (DOTANH) { v.x = tanhf(v.x); v.y = tanhf(v.y); v.z = tanhf(v.z); v.w = tanhf(v.w); }
            *(float4*)(C + (size_t)gr * NCOLS + col) = v;
        }
    }
}

// ---------------- elementwise GRU gate combine: g_rj[r][t] ----------------
__global__ void __launch_bounds__(256) combine_kernel(const float* __restrict__ rel_table, int R) {
    int idx = blockIdx.x * blockDim.x + threadIdx.x;
    if (idx >= R * DD) return;
    int r = idx >> 8, t = idx & 255;
    const float* gh = g_gh + (size_t)r * DD3;
    float rr = sigm(g_gi[t] + gh[t]);
    float zz = sigm(g_gi[DD + t] + gh[DD + t]);
    float nn = tanhf(g_gi[2 * DD + t] + rr * gh[2 * DD + t]);
    g_rj[idx] = (1.0f - zz) * nn + zz * rel_table[idx];
}

// ---------------- final assembly: one 64-thread group per output row ----------------
__global__ void __launch_bounds__(256) assemble_kernel(
    float* __restrict__ out,
    const float* __restrict__ entity_table,
    const int* __restrict__ rel_ids,
    const int* __restrict__ tails_state,
    const int* __restrict__ origin_ids,
    const int* __restrict__ seed_p,
    int N)
{
    long long gid = (long long)blockIdx.x * blockDim.x + threadIdx.x;
    int lane = (int)(gid & 63);
    long long n = gid >> 6;
    if (n >= N) return;

    int e = g_map[n];
    float4 v;
    if (e >= 0) {
        if (__ldg(tails_state + e) == 1) {
            const float4* src = (const float4*)(entity_table + (size_t)__ldg(origin_ids + e) * DD);
            v = __ldcs(src + lane);                     // streaming: random 1KB gathers, no reuse
        } else {
            const float4* src = (const float4*)(g_objTable + (size_t)__ldg(rel_ids + e) * DD);
            v = src[lane];                              // 1MB table: L2-resident
        }
    } else if ((int)n == *seed_p) {
        v = ((const float4*)g_sub)[lane];
    } else {
        v = make_float4(0.f, 0.f, 0.f, 0.f);
    }
    __stcs((float4*)out + n * (DD / 4) + lane, v);      // streaming store: don't thrash L2
}

// ---------------- launch ----------------
extern "C" void kernel_launch(void* const* d_in, const int* in_sizes, int n_in,
                              void* d_out, int out_size)
{
    const float* enc          = (const float*)d_in[0];
    const float* mask         = (const float*)d_in[1];
    const float* entity_table = (const float*)d_in[2];
    const float* rel_table    = (const float*)d_in[3];
    const float* W_ih         = (const float*)d_in[4];
    const float* W_hh         = (const float*)d_in[5];
    const float* b_ih         = (const float*)d_in[6];
    const float* b_hh         = (const float*)d_in[7];
    const float* sub_W        = (const float*)d_in[8];
    const float* sub_b        = (const float*)d_in[9];
    const float* obj_W        = (const float*)d_in[10];
    const float* obj_b        = (const float*)d_in[11];
    const int*   rel_ids      = (const int*)d_in[12];
    const int*   tail_ids     = (const int*)d_in[13];
    const int*   tails_state  = (const int*)d_in[14];
    const int*   origin_ids   = (const int*)d_in[15];
    const int*   seed_p       = (const int*)d_in[16];
    float*       out          = (float*)d_out;

    int E = in_sizes[12];
    int R = in_sizes[3] / DD;
    int N = out_size / DD;

    // 1) weight transposes (single merged kernel)
    transpose_kernel<<<dim3(8, 32), dim3(32, 32)>>>(W_hh, obj_W);

    // 2) serial chain (block 0) + map init (other blocks)
    int prep_blocks = 1 + (N + DD3 - 1) / DD3;
    prep_kernel<<<prep_blocks, DD3>>>(enc, mask, W_ih, W_hh, b_ih, b_hh, sub_W, sub_b, N);

    // 3) node->edge inverse map scatter (after init)
    map_scatter_kernel<<<(E + 511) / 512, 512>>>(tail_ids, E);

    // 4) gh = rel_emb @ W_hh.T + b_hh   [R,768]
    {
        float* ghp; cudaGetSymbolAddress((void**)&ghp, g_gh);
        float* whp; cudaGetSymbolAddress((void**)&whp, g_WhhT);
        gemm_kernel<DD3, false><<<dim3(DD3 / 64, (R + 63) / 64), 256>>>(
            rel_table, whp, b_hh, ghp, R);
    }

    // 5) GRU gate combine -> g_rj  [R,256]
    combine_kernel<<<(R * DD + 255) / 256, 256>>>(rel_table, R);

    // 6) obj_table = tanh(g_rj @ obj_W.T + obj_b)  [R,256]
    {
        float* rjp; cudaGetSymbolAddress((void**)&rjp, g_rj);
        float* owp; cudaGetSymbolAddress((void**)&owp, g_objWT);
        float* otp; cudaGetSymbolAddress((void**)&otp, g_objTable);
        gemm_kernel<DD, true><<<dim3(DD / 64, (R + 63) / 64), 256>>>(
            rjp, owp, obj_b, otp, R);
    }

    // 7) final gather/select/write of all N rows
    long long threads = (long long)N * 64;
    int blocks = (int)((threads + 255) / 256);
    assemble_kernel<<<blocks, 256>>>(out, entity_table, rel_ids, tails_state,
                                     origin_ids, seed_p, N);
}